// round 17
// baseline (speedup 1.0000x reference)
#include <cuda_runtime.h>
#include <cuda_fp16.h>
#include <math.h>
#include <stdint.h>

#define DEVINL __device__ __forceinline__

DEVINL float gelu_exact(float x) {
    return 0.5f * x * (1.0f + erff(x * 0.7071067811865475f));
}

// ---------------- mma.sync helpers (fp16 HMMA path) ----------------
DEVINL uint32_t smem_u32(const void* p) {
    uint32_t a;
    asm("{ .reg .u64 t; cvta.to.shared.u64 t, %1; cvt.u32.u64 %0, t; }" : "=r"(a) : "l"(p));
    return a;
}
DEVINL void ldmx4(uint32_t* r, uint32_t addr) {
    asm volatile("ldmatrix.sync.aligned.m8n8.x4.shared.b16 {%0,%1,%2,%3}, [%4];"
        : "=r"(r[0]), "=r"(r[1]), "=r"(r[2]), "=r"(r[3]) : "r"(addr));
}
DEVINL void ldmx4t(uint32_t* r, uint32_t addr) {
    asm volatile("ldmatrix.sync.aligned.m8n8.x4.trans.shared.b16 {%0,%1,%2,%3}, [%4];"
        : "=r"(r[0]), "=r"(r[1]), "=r"(r[2]), "=r"(r[3]) : "r"(addr));
}
DEVINL void mma_f16(float* d, const uint32_t* a, uint32_t b0, uint32_t b1) {
    asm volatile("mma.sync.aligned.m16n8k16.row.col.f32.f16.f16.f32 "
        "{%0,%1,%2,%3}, {%4,%5,%6,%7}, {%8,%9}, {%0,%1,%2,%3};"
        : "+f"(d[0]), "+f"(d[1]), "+f"(d[2]), "+f"(d[3])
        : "r"(a[0]), "r"(a[1]), "r"(a[2]), "r"(a[3]), "r"(b0), "r"(b1));
}
DEVINL uint32_t packhf(float lo, float hi) {
    uint32_t r;
    asm("cvt.rn.f16x2.f32 %0, %1, %2;" : "=r"(r) : "f"(hi), "f"(lo));
    return r;
}

DEVINL void cpasync16(uint32_t saddr, const void* g) {
    asm volatile("cp.async.cg.shared.global [%0], [%1], 16;" :: "r"(saddr), "l"(g));
}
#define CP_COMMIT() asm volatile("cp.async.commit_group;" ::: "memory")
#define CP_WAIT1()  asm volatile("cp.async.wait_group 1;" ::: "memory")
#define CP_WAIT0()  asm volatile("cp.async.wait_group 0;" ::: "memory")

// ---------------- problem constants ----------------
static const int M_TOK = 8192;
static const int D_MODEL = 768;
static const int D_FFN = 3072;

// ---------------- scratch (device globals) ----------------
__device__ __half s_xh[8192 * 768];
__device__ __half s_wqkvh[2304 * 768];
__device__ __half s_woh[768 * 768];
__device__ __half s_w1h[3072 * 768];
__device__ __half s_w2h[768 * 3072];
__device__ float  s_bqkv[2304];
__device__ __half s_qkv[8192 * 2304];
__device__ __half s_ch[8192 * 768];
__device__ __half s_n1h[8192 * 768];
__device__ __half s_hh[8192 * 3072];
__device__ float g_y1[8192 * 768];
__device__ float g_n1[8192 * 768];
__device__ float g_y2[8192 * 768];

// =====================================================================
// tohf_all: single-launch fp32 -> fp16 conversion of x + all weights.
// =====================================================================
#define X4   1572864               // 8192*768/4
#define W4   147456                // 768*768/4
#define F4   589824                // 3072*768/4
#define SEG1 (X4)
#define SEG2 (SEG1 + W4)
#define SEG3 (SEG2 + W4)
#define SEG4 (SEG3 + W4)
#define SEG5 (SEG4 + W4)
#define SEG6 (SEG5 + F4)
#define SEGT (SEG6 + F4)
#define WU32 294912                // 768*768 fp16 in u32 units

__global__ void __launch_bounds__(256) tohf_all(
    const float4* __restrict__ x,
    const float4* __restrict__ wq, const float4* __restrict__ wk,
    const float4* __restrict__ wv, const float4* __restrict__ wo,
    const float4* __restrict__ w1, const float4* __restrict__ w2,
    uint32_t* __restrict__ xh, uint32_t* __restrict__ wqkvh,
    uint32_t* __restrict__ woh, uint32_t* __restrict__ w1h,
    uint32_t* __restrict__ w2h)
{
    long i = (long)blockIdx.x * 256 + threadIdx.x;
    if (i >= SEGT) return;
    const float4* src;
    uint32_t* dst;
    long off;
    if (i < SEG1)      { src = x;  dst = xh;             off = i; }
    else if (i < SEG2) { src = wq; dst = wqkvh;          off = i - SEG1; }
    else if (i < SEG3) { src = wk; dst = wqkvh + WU32;   off = i - SEG2; }
    else if (i < SEG4) { src = wv; dst = wqkvh + 2*WU32; off = i - SEG3; }
    else if (i < SEG5) { src = wo; dst = woh;            off = i - SEG4; }
    else if (i < SEG6) { src = w1; dst = w1h;            off = i - SEG5; }
    else               { src = w2; dst = w2h;            off = i - SEG6; }
    float4 v = src[off];
    dst[2 * off]     = packhf(v.x, v.y);
    dst[2 * off + 1] = packhf(v.z, v.w);
}

// concat 3 x 768 biases into one 2304 buffer
__global__ void __launch_bounds__(256) concat3(
    const float* __restrict__ a, const float* __restrict__ b,
    const float* __restrict__ c, float* __restrict__ o)
{
    int i = blockIdx.x * 256 + threadIdx.x;
    if (i < 768) o[i] = a[i];
    else if (i < 1536) o[i] = b[i - 768];
    else if (i < 2304) o[i] = c[i - 1536];
}

// =====================================================================
// gemm_hf<EPI>: C[M,N] = A[M,K] @ B[N,K]^T, 1-pass fp16 HMMA.
// (unchanged from round 16)
// =====================================================================
#define G2_PAD 40
#define HF_BH 5120
#define HF_STG 10240
#define HF_SMEM (2 * HF_STG * 2)

template <int EPI>
__global__ void __launch_bounds__(256, 2) gemm_hf(
    const __half* __restrict__ Ah, const __half* __restrict__ Bh,
    const float* __restrict__ bias, const float* __restrict__ res,
    void* __restrict__ C0,
    float scale, int ncut, int M, int N, int K)
{
    extern __shared__ __half sgb[];
    const int tid = threadIdx.x;
    const int w = tid >> 5, lane = tid & 31;
    const int bn = blockIdx.x * 128;
    const int bm = blockIdx.y * 128;
    const uint32_t sb = smem_u32(sgb);

    const int lrow = lane & 15, lsel = lane >> 4;
    const int wm = (w & 1) * 64;
    const int wn = (w >> 1) * 32;
    const int NT = K >> 5;

    const int lr0 = tid >> 2;
    const int lr1 = lr0 + 64;
    const int lsg = (tid & 3) * 8;
    const uint32_t so0 = (uint32_t)((lr0 * G2_PAD + lsg) * 2);
    const uint32_t so1 = (uint32_t)((lr1 * G2_PAD + lsg) * 2);

    {
        uint32_t s0 = sb;
        cpasync16(s0 + so0, Ah + (long)(bm + lr0) * K + lsg);
        cpasync16(s0 + so1, Ah + (long)(bm + lr1) * K + lsg);
        cpasync16(s0 + HF_BH * 2 + so0, Bh + (long)(bn + lr0) * K + lsg);
        cpasync16(s0 + HF_BH * 2 + so1, Bh + (long)(bn + lr1) * K + lsg);
        CP_COMMIT();
    }

    float acc[4][4][4];
#pragma unroll
    for (int i = 0; i < 4; i++)
#pragma unroll
        for (int j = 0; j < 4; j++)
#pragma unroll
            for (int e = 0; e < 4; e++) acc[i][j][e] = 0.0f;

    for (int t = 0; t < NT; ++t) {
        if (t + 1 < NT) {
            uint32_t s0 = sb + ((t + 1) & 1) * (HF_STG * 2);
            int kofs = (t + 1) * 32;
            cpasync16(s0 + so0, Ah + (long)(bm + lr0) * K + kofs + lsg);
            cpasync16(s0 + so1, Ah + (long)(bm + lr1) * K + kofs + lsg);
            cpasync16(s0 + HF_BH * 2 + so0, Bh + (long)(bn + lr0) * K + kofs + lsg);
            cpasync16(s0 + HF_BH * 2 + so1, Bh + (long)(bn + lr1) * K + kofs + lsg);
            CP_COMMIT();
            CP_WAIT1();
        } else {
            CP_WAIT0();
        }
        __syncthreads();

        const uint32_t s0 = sb + (t & 1) * (HF_STG * 2);
#pragma unroll
        for (int kc = 0; kc < 2; kc++) {
            uint32_t bh[2][4];
#pragma unroll
            for (int ng = 0; ng < 2; ng++) {
                uint32_t ba = s0 + (uint32_t)((HF_BH + (wn + ng * 16 + lrow) * G2_PAD + kc * 16 + lsel * 8) * 2);
                ldmx4(bh[ng], ba);
            }
#pragma unroll
            for (int mt = 0; mt < 4; mt++) {
                uint32_t aa = s0 + (uint32_t)(((wm + mt * 16 + lrow) * G2_PAD + kc * 16 + lsel * 8) * 2);
                uint32_t ah[4];
                ldmx4(ah, aa);
#pragma unroll
                for (int ng = 0; ng < 2; ng++) {
                    mma_f16(acc[mt][ng * 2],     ah, bh[ng][0], bh[ng][2]);
                    mma_f16(acc[mt][ng * 2 + 1], ah, bh[ng][1], bh[ng][3]);
                }
            }
        }
        __syncthreads();
    }

    const int er = lane >> 2;
    const int ec = (lane & 3) * 2;
#pragma unroll
    for (int mt = 0; mt < 4; mt++) {
        long r0 = bm + wm + mt * 16 + er;
        long r1 = r0 + 8;
#pragma unroll
        for (int nt = 0; nt < 4; nt++) {
            int cn = bn + wn + nt * 8 + ec;
            float b0 = bias[cn], b1 = bias[cn + 1];
            float x0 = acc[mt][nt][0] + b0, x1 = acc[mt][nt][1] + b1;
            float x2 = acc[mt][nt][2] + b0, x3 = acc[mt][nt][3] + b1;
            if (EPI == 0) {
                float sc = (cn < ncut) ? scale : 1.0f;
                x0 *= sc; x1 *= sc; x2 *= sc; x3 *= sc;
                *(uint32_t*)((__half*)C0 + r0 * N + cn) = packhf(x0, x1);
                *(uint32_t*)((__half*)C0 + r1 * N + cn) = packhf(x2, x3);
            } else if (EPI == 1) {
                x0 = gelu_exact(x0); x1 = gelu_exact(x1);
                x2 = gelu_exact(x2); x3 = gelu_exact(x3);
                *(uint32_t*)((__half*)C0 + r0 * N + cn) = packhf(x0, x1);
                *(uint32_t*)((__half*)C0 + r1 * N + cn) = packhf(x2, x3);
            } else {
                float2 rv0 = *(const float2*)(res + r0 * N + cn);
                float2 rv1 = *(const float2*)(res + r1 * N + cn);
                *(float2*)((float*)C0 + r0 * N + cn) = make_float2(x0 + rv0.x, x1 + rv0.y);
                *(float2*)((float*)C0 + r1 * N + cn) = make_float2(x2 + rv1.x, x3 + rv1.y);
            }
        }
    }
}

// =====================================================================
// flash attention v8 (fp16 HMMA): 128 threads / 4 warps, 32 q-rows per
// warp (mt=2). Per-16-key-chunk fused S->softmax->PV (S regs 64->16,
// pa 32->8) + cp.async K/V staging (no register prefetch).
// ~150 regs -> __launch_bounds__(128,3): 12 warps/SM.
// Q/K/V row stride ld (2304 for fused-QKV buffer). Writes ctx fp16.
// =====================================================================
#define FL8_SMEM ((128 * 72 + 4 * 64 * 72) * 2)

__global__ void __launch_bounds__(128, 3) flash_attn_mma(
    const __half* __restrict__ Q,
    const __half* __restrict__ Kg,
    const __half* __restrict__ Vg,
    __half* __restrict__ Oh,
    int ld)
{
    extern __shared__ __half smh[];
    __half* Qs  = smh;
    __half* Ks0 = Qs + 128 * 72;
    __half* Vs0 = Ks0 + 64 * 72;
    __half* Ks1 = Vs0 + 64 * 72;
    __half* Vs1 = Ks1 + 64 * 72;

    const int tid = threadIdx.x;           // 0..127
    const int w = tid >> 5;                // 0..3
    const int lane = tid & 31;
    const int bhead = blockIdx.y;
    const int b = bhead / 12;
    const int h = bhead - b * 12;
    const int q0 = blockIdx.x * 128;
    const long rowbase = (long)b * 4096;

    const __half* Qb = Q + (rowbase + q0) * ld + h * 64;
    const __half* KB = Kg + rowbase * ld + h * 64;
    const __half* VB = Vg + rowbase * ld + h * 64;

    // staging mapping: chunk idx = tid + i*128; row = idx>>3, seg = idx&7
    const int srow = tid >> 3;             // 0..15
    const int sseg = tid & 7;

    // ---- stage Q (128 x 64): 8 chunks per thread ----
#pragma unroll
    for (int i = 0; i < 8; i++) {
        int row = srow + i * 16;
        *(uint4*)(Qs + row * 72 + sseg * 8) = *(const uint4*)(Qb + (long)row * ld + sseg * 8);
    }
    __syncthreads();

    const int lrow = lane & 15, lsel = lane >> 4;
    uint32_t qf[2][4][4];
    {
        uint32_t qbase = smem_u32(Qs);
#pragma unroll
        for (int mt = 0; mt < 2; mt++)
#pragma unroll
            for (int kc = 0; kc < 4; kc++) {
                uint32_t addr = qbase + (uint32_t)(((w * 32 + mt * 16 + lrow) * 72 + kc * 16 + lsel * 8) * 2);
                ldmx4(qf[mt][kc], addr);
            }
    }

    const uint32_t k0b = smem_u32(Ks0), v0b = smem_u32(Vs0);
    const uint32_t k1b = smem_u32(Ks1), v1b = smem_u32(Vs1);
    const uint32_t soff = (uint32_t)((srow * 72 + sseg * 8) * 2);

    // ---- cp.async stage K/V tile 0 into buffer 0 ----
    {
#pragma unroll
        for (int i = 0; i < 4; i++) {
            long row = srow + i * 16;
            cpasync16(k0b + soff + (uint32_t)(i * 16 * 72 * 2), KB + row * ld + sseg * 8);
            cpasync16(v0b + soff + (uint32_t)(i * 16 * 72 * 2), VB + row * ld + sseg * 8);
        }
        CP_COMMIT();
    }

    float ctx[2][8][4];
#pragma unroll
    for (int mt = 0; mt < 2; mt++)
#pragma unroll
        for (int i = 0; i < 8; i++)
#pragma unroll
            for (int j = 0; j < 4; j++) ctx[mt][i][j] = 0.0f;
    float l0[2] = {0.0f, 0.0f}, l1[2] = {0.0f, 0.0f};

    for (int kt = 0; kt < 64; ++kt) {
        const uint32_t kb = (kt & 1) ? k1b : k0b;
        const uint32_t vb = (kt & 1) ? v1b : v0b;

        if (kt + 1 < 64) {
            const uint32_t kbn = (kt & 1) ? k0b : k1b;
            const uint32_t vbn = (kt & 1) ? v0b : v1b;
            const __half* Kn = KB + (long)(kt + 1) * 64 * ld;
            const __half* Vn = VB + (long)(kt + 1) * 64 * ld;
#pragma unroll
            for (int i = 0; i < 4; i++) {
                long row = srow + i * 16;
                cpasync16(kbn + soff + (uint32_t)(i * 16 * 72 * 2), Kn + row * ld + sseg * 8);
                cpasync16(vbn + soff + (uint32_t)(i * 16 * 72 * 2), Vn + row * ld + sseg * 8);
            }
            CP_COMMIT();
            CP_WAIT1();
        } else {
            CP_WAIT0();
        }
        __syncthreads();

        // ---- per 16-key chunk: S -> softmax -> PV (fused) ----
#pragma unroll
        for (int np = 0; np < 4; np++) {
            float S[2][2][4];
#pragma unroll
            for (int mt = 0; mt < 2; mt++)
#pragma unroll
                for (int j = 0; j < 2; j++)
#pragma unroll
                    for (int e = 0; e < 4; e++) S[mt][j][e] = 0.0f;

#pragma unroll
            for (int kc = 0; kc < 4; kc++) {
                uint32_t kf[4];
                uint32_t addr = kb + (uint32_t)(((np * 16 + lrow) * 72 + kc * 16 + lsel * 8) * 2);
                ldmx4(kf, addr);
#pragma unroll
                for (int mt = 0; mt < 2; mt++) {
                    mma_f16(S[mt][0], qf[mt][kc], kf[0], kf[2]);
                    mma_f16(S[mt][1], qf[mt][kc], kf[1], kf[3]);
                }
            }

            uint32_t pa[2][4];
#pragma unroll
            for (int mt = 0; mt < 2; mt++) {
                float e0 = __expf(S[mt][0][0]);
                float e1 = __expf(S[mt][0][1]);
                float e2 = __expf(S[mt][0][2]);
                float e3 = __expf(S[mt][0][3]);
                float f0 = __expf(S[mt][1][0]);
                float f1 = __expf(S[mt][1][1]);
                float f2 = __expf(S[mt][1][2]);
                float f3 = __expf(S[mt][1][3]);
                l0[mt] += (e0 + e1) + (f0 + f1);
                l1[mt] += (e2 + e3) + (f2 + f3);
                pa[mt][0] = packhf(e0, e1);
                pa[mt][1] = packhf(e2, e3);
                pa[mt][2] = packhf(f0, f1);
                pa[mt][3] = packhf(f2, f3);
            }

#pragma unroll
            for (int dnp = 0; dnp < 4; dnp++) {
                uint32_t vf[4];
                uint32_t addr = vb + (uint32_t)(((np * 16 + lrow) * 72 + dnp * 16 + lsel * 8) * 2);
                ldmx4t(vf, addr);
#pragma unroll
                for (int mt = 0; mt < 2; mt++) {
                    mma_f16(ctx[mt][2 * dnp],     pa[mt], vf[0], vf[1]);
                    mma_f16(ctx[mt][2 * dnp + 1], pa[mt], vf[2], vf[3]);
                }
            }
        }
        __syncthreads();
    }

    // ---- reduce l over quad lanes, normalize, write ----
    const int r0 = lane >> 2;
    const int cc = (lane & 3) * 2;
    const long obase = (rowbase + q0) * 768 + h * 64;
#pragma unroll
    for (int mt = 0; mt < 2; mt++) {
        float a = l0[mt], c = l1[mt];
        a += __shfl_xor_sync(0xffffffffu, a, 1);
        a += __shfl_xor_sync(0xffffffffu, a, 2);
        c += __shfl_xor_sync(0xffffffffu, c, 1);
        c += __shfl_xor_sync(0xffffffffu, c, 2);
        const float inv0 = 1.0f / a;
        const float inv1 = 1.0f / c;
        const long rr = w * 32 + mt * 16 + r0;
#pragma unroll
        for (int nt = 0; nt < 8; nt++) {
            long o0 = obase + rr * 768 + nt * 8 + cc;
            long o1 = obase + (rr + 8) * 768 + nt * 8 + cc;
            *(uint32_t*)(Oh + o0) = packhf(ctx[mt][nt][0] * inv0, ctx[mt][nt][1] * inv0);
            *(uint32_t*)(Oh + o1) = packhf(ctx[mt][nt][2] * inv1, ctx[mt][nt][3] * inv1);
        }
    }
}

// =====================================================================
// LayerNorm: warp-per-row, 8 rows per block. HOUT=1 also writes fp16.
// =====================================================================
template <int HOUT>
__global__ void __launch_bounds__(256) layernorm_w(
    const float* __restrict__ X,
    const float* __restrict__ g,
    const float* __restrict__ bta,
    float* __restrict__ Y,
    __half* __restrict__ Yh)
{
    const int wid = threadIdx.x >> 5;
    const int lane = threadIdx.x & 31;
    const long row = (long)blockIdx.x * 8 + wid;
    const float* x = X + row * 768;

    float4 v[6];
    float s = 0.0f, ss = 0.0f;
#pragma unroll
    for (int i = 0; i < 6; i++) {
        v[i] = *(const float4*)(x + (i * 32 + lane) * 4);
        s += (v[i].x + v[i].y) + (v[i].z + v[i].w);
        ss += (v[i].x * v[i].x + v[i].y * v[i].y) + (v[i].z * v[i].z + v[i].w * v[i].w);
    }
#pragma unroll
    for (int d = 16; d; d >>= 1) {
        s += __shfl_xor_sync(0xffffffffu, s, d);
        ss += __shfl_xor_sync(0xffffffffu, ss, d);
    }
    const float invD = 1.0f / 768.0f;
    const float mu = s * invD;
    const float var = ss * invD - mu * mu;
    const float rstd = rsqrtf(var + 1e-5f);

    float* y = Y + row * 768;
#pragma unroll
    for (int i = 0; i < 6; i++) {
        int c = (i * 32 + lane) * 4;
        float4 gv = *(const float4*)(g + c);
        float4 bv = *(const float4*)(bta + c);
        float o0 = (v[i].x - mu) * rstd * gv.x + bv.x;
        float o1 = (v[i].y - mu) * rstd * gv.y + bv.y;
        float o2 = (v[i].z - mu) * rstd * gv.z + bv.z;
        float o3 = (v[i].w - mu) * rstd * gv.w + bv.w;
        *(float4*)(y + c) = make_float4(o0, o1, o2, o3);
        if (HOUT) {
            *(uint32_t*)(Yh + row * 768 + c)     = packhf(o0, o1);
            *(uint32_t*)(Yh + row * 768 + c + 2) = packhf(o2, o3);
        }
    }
}

// =====================================================================
// host launcher (graph-capturable)
// =====================================================================
extern "C" void kernel_launch(void* const* d_in, const int* in_sizes, int n_in,
                              void* d_out, int out_size)
{
    (void)in_sizes; (void)n_in; (void)out_size;
    const float* x   = (const float*)d_in[0];
    const float* wq  = (const float*)d_in[1];
    const float* bq  = (const float*)d_in[2];
    const float* wk  = (const float*)d_in[3];
    const float* bk  = (const float*)d_in[4];
    const float* wv  = (const float*)d_in[5];
    const float* bv  = (const float*)d_in[6];
    const float* wo  = (const float*)d_in[7];
    const float* bo  = (const float*)d_in[8];
    const float* w1  = (const float*)d_in[9];
    const float* b1  = (const float*)d_in[10];
    const float* w2  = (const float*)d_in[11];
    const float* b2  = (const float*)d_in[12];
    const float* g1  = (const float*)d_in[13];
    const float* be1 = (const float*)d_in[14];
    const float* g2  = (const float*)d_in[15];
    const float* be2 = (const float*)d_in[16];
    float* out = (float*)d_out;

    __half *xh, *wqkvh, *woh, *w1h, *w2h, *qkv, *ch, *n1h, *hh;
    float *bqkv, *y1, *n1, *y2;
    cudaGetSymbolAddress((void**)&xh,    s_xh);
    cudaGetSymbolAddress((void**)&wqkvh, s_wqkvh);
    cudaGetSymbolAddress((void**)&woh,   s_woh);
    cudaGetSymbolAddress((void**)&w1h,   s_w1h);
    cudaGetSymbolAddress((void**)&w2h,   s_w2h);
    cudaGetSymbolAddress((void**)&bqkv,  s_bqkv);
    cudaGetSymbolAddress((void**)&qkv,   s_qkv);
    cudaGetSymbolAddress((void**)&ch,    s_ch);
    cudaGetSymbolAddress((void**)&n1h,   s_n1h);
    cudaGetSymbolAddress((void**)&hh,    s_hh);
    cudaGetSymbolAddress((void**)&y1,    g_y1);
    cudaGetSymbolAddress((void**)&n1,    g_n1);
    cudaGetSymbolAddress((void**)&y2,    g_y2);

    cudaFuncSetAttribute(flash_attn_mma, cudaFuncAttributeMaxDynamicSharedMemorySize, FL8_SMEM);
    cudaFuncSetAttribute((gemm_hf<0>), cudaFuncAttributeMaxDynamicSharedMemorySize, HF_SMEM);
    cudaFuncSetAttribute((gemm_hf<1>), cudaFuncAttributeMaxDynamicSharedMemorySize, HF_SMEM);
    cudaFuncSetAttribute((gemm_hf<2>), cudaFuncAttributeMaxDynamicSharedMemorySize, HF_SMEM);

    dim3 blk(256);

    // ---- conversions ----
    tohf_all<<<(SEGT + 255) / 256, blk>>>(
        (const float4*)x, (const float4*)wq, (const float4*)wk,
        (const float4*)wv, (const float4*)wo, (const float4*)w1, (const float4*)w2,
        (uint32_t*)xh, (uint32_t*)wqkvh, (uint32_t*)woh, (uint32_t*)w1h, (uint32_t*)w2h);
    concat3<<<9, blk>>>(bq, bk, bv, bqkv);

    dim3 gqkv(2304 / 128, M_TOK / 128);  // (18, 64)
    dim3 g768(768 / 128, M_TOK / 128);   // (6, 64)
    dim3 gffn(3072 / 128, M_TOK / 128);  // (24, 64)

    // ---- fused QKV, 1-pass fp16 (q section scaled 1/8) ----
    gemm_hf<0><<<gqkv, blk, HF_SMEM>>>(xh, wqkvh, bqkv, nullptr,
                                       qkv, 0.125f, 768, M_TOK, 2304, D_MODEL);
    // ---- attention (ld = 2304), 128-thread blocks, 3 blocks/SM ----
    flash_attn_mma<<<dim3(32, 24), dim3(128), FL8_SMEM>>>(qkv, qkv + 768, qkv + 1536, ch, 2304);
    // ---- O-proj, 1-pass fp16, + residual(x) -> y1 ----
    gemm_hf<2><<<g768, blk, HF_SMEM>>>(ch, woh, bo, x, y1,
                                       1.0f, 0, M_TOK, D_MODEL, D_MODEL);
    layernorm_w<1><<<M_TOK / 8, blk>>>(y1, g1, be1, n1, n1h);
    // ---- FFN, 1-pass fp16 ----
    gemm_hf<1><<<gffn, blk, HF_SMEM>>>(n1h, w1h, b1, nullptr, hh,
                                       1.0f, 0, M_TOK, D_FFN, D_MODEL);
    gemm_hf<2><<<g768, blk, HF_SMEM>>>(hh, w2h, b2, n1, y2,
                                       1.0f, 0, M_TOK, D_MODEL, D_FFN);
    layernorm_w<0><<<M_TOK / 8, blk>>>(y2, g2, be2, out, nullptr);
}